// round 2
// baseline (speedup 1.0000x reference)
#include <cuda_runtime.h>
#include <math.h>

#define D_MODEL 4096
#define N_EXP   64
#define TOPK    8
#define TILE    128   // smem staging tile (d elements)
#define INNER   64    // inner accumulation chunk (d elements) for accuracy
#define TPB     64    // == N_EXP, one thread stages one expert's W rows

// One thread = one token. 64 fp32 logits in 32 packed f32x2 master accumulators.
// Two-level accumulation: per-64d chunk accumulators flushed into masters,
// cutting fp32 accumulation error ~10x (needed: top-k index ranking must match
// the reference to ~1e-6 logit accuracy or indices flip).
__global__ void __launch_bounds__(TPB)
router_kernel(const float* __restrict__ x, const float* __restrict__ W,
              float* __restrict__ out, int n_tokens, long long out_size)
{
    __shared__ float sW[TILE * N_EXP];

    const int t = threadIdx.x;
    const int n = blockIdx.x * TPB + t;
    const bool active = (n < n_tokens);

    unsigned long long acc[N_EXP / 2];
#pragma unroll
    for (int i = 0; i < N_EXP / 2; i++) acc[i] = 0ull;

    const float* xrow = x + (size_t)n * D_MODEL;

    for (int d0 = 0; d0 < D_MODEL; d0 += TILE) {
        // ---- cooperative W tile load, transposed: sW[d][e] = W[e][d0+d] ----
        {
            const float4* wsrc = (const float4*)(W + (size_t)t * D_MODEL + d0);
#pragma unroll
            for (int j = 0; j < TILE / 4; j++) {
                float4 v = wsrc[j];
                sW[(j * 4 + 0) * N_EXP + t] = v.x;
                sW[(j * 4 + 1) * N_EXP + t] = v.y;
                sW[(j * 4 + 2) * N_EXP + t] = v.z;
                sW[(j * 4 + 3) * N_EXP + t] = v.w;
            }
        }
        __syncthreads();

        if (active) {
#pragma unroll
            for (int h = 0; h < TILE / INNER; h++) {
                // fresh chunk accumulators (accuracy level 1)
                unsigned long long cacc[N_EXP / 2];
#pragma unroll
                for (int i = 0; i < N_EXP / 2; i++) cacc[i] = 0ull;

                const int base = d0 + h * INNER;
#pragma unroll 4
                for (int i4 = 0; i4 < INNER; i4 += 4) {
                    float4 xv = *(const float4*)(xrow + base + i4);
                    float xs[4] = {xv.x, xv.y, xv.z, xv.w};
#pragma unroll
                    for (int k = 0; k < 4; k++) {
                        unsigned long long xp;
                        unsigned int xb = __float_as_uint(xs[k]);
                        asm("mov.b64 %0, {%1, %1};" : "=l"(xp) : "r"(xb));
                        const ulonglong2* wrow =
                            (const ulonglong2*)(sW + (h * INNER + i4 + k) * N_EXP);
#pragma unroll
                        for (int q = 0; q < 16; q++) {
                            ulonglong2 w = wrow[q];  // experts 4q..4q+3
                            asm("fma.rn.f32x2 %0, %1, %2, %0;"
                                : "+l"(cacc[2 * q])     : "l"(w.x), "l"(xp));
                            asm("fma.rn.f32x2 %0, %1, %2, %0;"
                                : "+l"(cacc[2 * q + 1]) : "l"(w.y), "l"(xp));
                        }
                    }
                }
                // flush chunk -> master (accuracy level 2)
#pragma unroll
                for (int i = 0; i < N_EXP / 2; i++) {
                    asm("add.rn.f32x2 %0, %0, %1;"
                        : "+l"(acc[i]) : "l"(cacc[i]));
                }
            }
        }
        __syncthreads();
    }

    if (!active) return;

    // ---- unpack logits ----
    float p[N_EXP];
#pragma unroll
    for (int a = 0; a < N_EXP / 2; a++) {
        float lo, hi;
        asm("mov.b64 {%0, %1}, %2;" : "=f"(lo), "=f"(hi) : "l"(acc[a]));
        p[2 * a] = lo;
        p[2 * a + 1] = hi;
    }

    // ---- softmax over 64 experts (registers) ----
    float m = p[0];
#pragma unroll
    for (int e = 1; e < N_EXP; e++) m = fmaxf(m, p[e]);
    float s = 0.f;
#pragma unroll
    for (int e = 0; e < N_EXP; e++) { p[e] = expf(p[e] - m); s += p[e]; }
    float inv = 1.0f / s;
#pragma unroll
    for (int e = 0; e < N_EXP; e++) p[e] *= inv;

    const long long NK = (long long)n_tokens * TOPK;
    const long long full = 2 * NK + (long long)n_tokens * N_EXP;

    // ---- write probs (layout: [idx | weights | probs]) ----
    if (out_size >= full) {
        float* pout = out + 2 * NK + (size_t)n * N_EXP;
#pragma unroll
        for (int e = 0; e < N_EXP; e++) pout[e] = p[e];
    }

    // ---- stable top-8 insertion sort (matches lax.top_k tie-breaking) ----
    float tv[TOPK];
    int   ti[TOPK];
#pragma unroll
    for (int k = 0; k < TOPK; k++) { tv[k] = -1.0f; ti[k] = 0; }
#pragma unroll
    for (int e = 0; e < N_EXP; e++) {
        float v = p[e];
        if (v > tv[TOPK - 1]) {
            tv[TOPK - 1] = v;
            ti[TOPK - 1] = e;
#pragma unroll
            for (int j = TOPK - 1; j > 0; j--) {
                if (tv[j] > tv[j - 1]) {
                    float tf = tv[j]; tv[j] = tv[j - 1]; tv[j - 1] = tf;
                    int   tn = ti[j]; ti[j] = ti[j - 1]; ti[j - 1] = tn;
                }
            }
        }
    }

    float ssum = 0.f;
#pragma unroll
    for (int k = 0; k < TOPK; k++) ssum += tv[k];
    float winv = 1.0f / (ssum + 1e-9f);

    if (out_size >= 2 * NK) {
#pragma unroll
        for (int k = 0; k < TOPK; k++) {
            out[(size_t)n * TOPK + k]      = (float)ti[k];
            out[NK + (size_t)n * TOPK + k] = tv[k] * winv;
        }
    } else if (out_size >= NK) {
#pragma unroll
        for (int k = 0; k < TOPK; k++)
            out[(size_t)n * TOPK + k] = (float)ti[k];
    }
}

extern "C" void kernel_launch(void* const* d_in, const int* in_sizes, int n_in,
                              void* d_out, int out_size)
{
    const float* x = (const float*)d_in[0];
    const float* W = (const float*)d_in[1];
    int n_tokens = in_sizes[0] / D_MODEL;   // 16384
    int grid = (n_tokens + TPB - 1) / TPB;  // 256
    router_kernel<<<grid, TPB>>>(x, W, (float*)d_out, n_tokens,
                                 (long long)out_size);
}

// round 3
// speedup vs baseline: 1.4674x; 1.4674x over previous
#include <cuda_runtime.h>
#include <math.h>
#include <stdint.h>

#define D_MODEL 4096
#define N_EXP   64
#define TOPK    8
#define BM      64            // tokens per CTA
#define TD      64            // d-depth per tile
#define TPB     128
#define NTILES  (D_MODEL / TD)
#define XROW    68            // padded floats per x_s row (272B, 16B-aligned)
#define XBYTES  (BM * XROW * 4)        // 17408
#define WBYTES  (TD * N_EXP * 4)       // 16384
#define STAGEB  (XBYTES + WBYTES)      // 33792
#define SMEMB   (2 * STAGEB)           // 67584
#define LROW    65            // logits row pad (bank-conflict-free epilogue)

__device__ float Wt_g[D_MODEL * N_EXP];   // W transposed: Wt[d][e]

__global__ void transpose_W(const float* __restrict__ W)
{
    int idx = blockIdx.x * blockDim.x + threadIdx.x;  // = e*4096 + d
    if (idx < N_EXP * D_MODEL) {
        int e = idx >> 12;
        int d = idx & (D_MODEL - 1);
        Wt_g[d * N_EXP + e] = W[idx];
    }
}

__device__ __forceinline__ void cpa16(uint32_t dst, const void* src)
{
    asm volatile("cp.async.ca.shared.global [%0], [%1], 16;\n"
                 :: "r"(dst), "l"(src));
}
__device__ __forceinline__ void cpa_commit()
{
    asm volatile("cp.async.commit_group;\n");
}
template <int N> __device__ __forceinline__ void cpa_wait()
{
    asm volatile("cp.async.wait_group %0;\n" :: "n"(N));
}

__device__ __forceinline__ void load_tile(uint32_t sbase, const float* __restrict__ x,
                                          int blk_tok, int d0, int n_tokens, int t)
{
    // x tile: 64 token-rows x 256B, dst rows padded to 272B
#pragma unroll
    for (int i = 0; i < (BM * 16) / TPB; i++) {
        int c   = t + i * TPB;
        int tok = c >> 4, seg = c & 15;
        int tg  = blk_tok + tok; if (tg >= n_tokens) tg = n_tokens - 1;
        cpa16(sbase + tok * (XROW * 4) + seg * 16,
              x + (size_t)tg * D_MODEL + d0 + seg * 4);
    }
    // W tile: 64 d-rows x 256B, contiguous both sides
    uint32_t wb = sbase + XBYTES;
#pragma unroll
    for (int i = 0; i < (TD * 16) / TPB; i++) {
        int c  = t + i * TPB;
        int dr = c >> 4, seg = c & 15;
        cpa16(wb + dr * 256 + seg * 16,
              Wt_g + (size_t)(d0 + dr) * N_EXP + seg * 4);
    }
}

__global__ void __launch_bounds__(TPB)
router_kernel(const float* __restrict__ x, float* __restrict__ out,
              int n_tokens, long long out_size)
{
    extern __shared__ char smem[];
    const uint32_t sb = (uint32_t)__cvta_generic_to_shared(smem);

    const int t   = threadIdx.x;
    const int tm4 = (t >> 3) * 4;   // 4 tokens of this thread
    const int tn8 = (t & 7) * 8;    // 8 experts of this thread
    const int blk_tok = blockIdx.x * BM;

    unsigned long long master[16];
#pragma unroll
    for (int i = 0; i < 16; i++) master[i] = 0ull;

    load_tile(sb, x, blk_tok, 0, n_tokens, t);
    cpa_commit();

    for (int tile = 0; tile < NTILES; tile++) {
        const int cur = tile & 1;
        if (tile + 1 < NTILES) {
            load_tile(sb + (cur ^ 1) * STAGEB, x, blk_tok, (tile + 1) * TD,
                      n_tokens, t);
            cpa_commit();
            cpa_wait<1>();
        } else {
            cpa_wait<0>();
        }
        __syncthreads();

        const float* x_s = (const float*)(smem + cur * STAGEB);
        const float* W_s = (const float*)(smem + cur * STAGEB + XBYTES);

        unsigned long long cacc[16];
#pragma unroll
        for (int i = 0; i < 16; i++) cacc[i] = 0ull;

#pragma unroll 2
        for (int d4 = 0; d4 < TD; d4 += 4) {
            float xr0[4], xr1[4], xr2[4], xr3[4];
            *(float4*)xr0 = *(const float4*)(x_s + (tm4 + 0) * XROW + d4);
            *(float4*)xr1 = *(const float4*)(x_s + (tm4 + 1) * XROW + d4);
            *(float4*)xr2 = *(const float4*)(x_s + (tm4 + 2) * XROW + d4);
            *(float4*)xr3 = *(const float4*)(x_s + (tm4 + 3) * XROW + d4);
#pragma unroll
            for (int dd = 0; dd < 4; dd++) {
                const float* wrow = W_s + (d4 + dd) * N_EXP + tn8;
                ulonglong2 w0 = *(const ulonglong2*)(wrow);
                ulonglong2 w1 = *(const ulonglong2*)(wrow + 4);
                float xv[4] = {xr0[dd], xr1[dd], xr2[dd], xr3[dd]};
#pragma unroll
                for (int j = 0; j < 4; j++) {
                    unsigned long long xp;
                    unsigned int xb = __float_as_uint(xv[j]);
                    asm("mov.b64 %0, {%1, %1};" : "=l"(xp) : "r"(xb));
                    asm("fma.rn.f32x2 %0, %1, %2, %0;"
                        : "+l"(cacc[j * 4 + 0]) : "l"(w0.x), "l"(xp));
                    asm("fma.rn.f32x2 %0, %1, %2, %0;"
                        : "+l"(cacc[j * 4 + 1]) : "l"(w0.y), "l"(xp));
                    asm("fma.rn.f32x2 %0, %1, %2, %0;"
                        : "+l"(cacc[j * 4 + 2]) : "l"(w1.x), "l"(xp));
                    asm("fma.rn.f32x2 %0, %1, %2, %0;"
                        : "+l"(cacc[j * 4 + 3]) : "l"(w1.y), "l"(xp));
                }
            }
        }
        // flush chunk -> master (two-level accumulation for top-k accuracy)
#pragma unroll
        for (int i = 0; i < 16; i++)
            asm("add.rn.f32x2 %0, %0, %1;" : "+l"(master[i]) : "l"(cacc[i]));

        __syncthreads();
    }

    // ---- epilogue: gather logits per token in smem ----
    float* L = (float*)smem;   // [BM][LROW]
#pragma unroll
    for (int j = 0; j < 4; j++) {
#pragma unroll
        for (int q = 0; q < 4; q++) {
            float lo, hi;
            asm("mov.b64 {%0, %1}, %2;" : "=f"(lo), "=f"(hi)
                : "l"(master[j * 4 + q]));
            L[(tm4 + j) * LROW + tn8 + 2 * q]     = lo;
            L[(tm4 + j) * LROW + tn8 + 2 * q + 1] = hi;
        }
    }
    __syncthreads();

    if (t < BM) {
        const int n = blk_tok + t;
        if (n < n_tokens) {
            float p[N_EXP];
            const float* Lr = L + t * LROW;
#pragma unroll
            for (int e = 0; e < N_EXP; e++) p[e] = Lr[e];

            float m = p[0];
#pragma unroll
            for (int e = 1; e < N_EXP; e++) m = fmaxf(m, p[e]);
            float s = 0.f;
#pragma unroll
            for (int e = 0; e < N_EXP; e++) { p[e] = expf(p[e] - m); s += p[e]; }
            float inv = 1.0f / s;
#pragma unroll
            for (int e = 0; e < N_EXP; e++) p[e] *= inv;

            const long long NK   = (long long)n_tokens * TOPK;
            const long long full = 2 * NK + (long long)n_tokens * N_EXP;

            if (out_size >= full) {
                float* pout = out + 2 * NK + (size_t)n * N_EXP;
#pragma unroll
                for (int e = 0; e < N_EXP; e++) pout[e] = p[e];
            }

            float tv[TOPK];
            int   ti[TOPK];
#pragma unroll
            for (int k = 0; k < TOPK; k++) { tv[k] = -1.0f; ti[k] = 0; }
#pragma unroll
            for (int e = 0; e < N_EXP; e++) {
                float v = p[e];
                if (v > tv[TOPK - 1]) {
                    tv[TOPK - 1] = v;
                    ti[TOPK - 1] = e;
#pragma unroll
                    for (int j = TOPK - 1; j > 0; j--) {
                        if (tv[j] > tv[j - 1]) {
                            float tf = tv[j]; tv[j] = tv[j - 1]; tv[j - 1] = tf;
                            int   tn = ti[j]; ti[j] = ti[j - 1]; ti[j - 1] = tn;
                        }
                    }
                }
            }

            float ssum = 0.f;
#pragma unroll
            for (int k = 0; k < TOPK; k++) ssum += tv[k];
            float winv = 1.0f / (ssum + 1e-9f);

            if (out_size >= 2 * NK) {
#pragma unroll
                for (int k = 0; k < TOPK; k++) {
                    out[(size_t)n * TOPK + k]      = (float)ti[k];
                    out[NK + (size_t)n * TOPK + k] = tv[k] * winv;
                }
            } else if (out_size >= NK) {
#pragma unroll
                for (int k = 0; k < TOPK; k++)
                    out[(size_t)n * TOPK + k] = (float)ti[k];
            }
        }
    }
}

extern "C" void kernel_launch(void* const* d_in, const int* in_sizes, int n_in,
                              void* d_out, int out_size)
{
    const float* x = (const float*)d_in[0];
    const float* W = (const float*)d_in[1];
    int n_tokens = in_sizes[0] / D_MODEL;            // 16384

    cudaFuncSetAttribute(router_kernel,
                         cudaFuncAttributeMaxDynamicSharedMemorySize, SMEMB);

    transpose_W<<<(N_EXP * D_MODEL + 255) / 256, 256>>>(W);

    int grid = (n_tokens + BM - 1) / BM;             // 256
    router_kernel<<<grid, TPB, SMEMB>>>(x, (float*)d_out, n_tokens,
                                        (long long)out_size);
}

// round 6
// speedup vs baseline: 3.2252x; 2.1979x over previous
#include <cuda_runtime.h>
#include <math.h>
#include <stdint.h>

#define D_MODEL 4096
#define N_EXP   64
#define TOPK    8
#define M_CTA   128
#define TPB     256
#define KC      32
#define NCH     (D_MODEL / KC)     // 128

#define XROW    36                 // padded floats per x smem row
#define WROW    72                 // padded floats per W smem row
#define XTB     (M_CTA * XROW * 4) // 18432
#define WTB     (KC * WROW * 4)    // 9216
#define STAGE   (XTB + 2 * WTB)    // 36864
#define SMEMB   (2 * STAGE)        // 73728
#define LROW    66                 // logits pad (even -> float2-aligned)

// W transposed [d][e], pre-split into tf32-format hi/lo parts
__device__ float Wth_g[D_MODEL * N_EXP];
__device__ float Wtl_g[D_MODEL * N_EXP];

__device__ __forceinline__ float to_tf32(float x) {
    float r;
    asm("cvt.rna.tf32.f32 %0, %1;" : "=f"(r) : "f"(x));
    return r;
}

__global__ void split_W(const float* __restrict__ W)
{
    int i = blockIdx.x * 256 + threadIdx.x;
    if (i < N_EXP * D_MODEL) {
        int d = i >> 6, e = i & 63;
        float w = W[(size_t)e * D_MODEL + d];
        float h = to_tf32(w);
        Wth_g[i] = h;
        Wtl_g[i] = to_tf32(w - h);
    }
}

__device__ __forceinline__ void cpa16(uint32_t dst, const void* src) {
    asm volatile("cp.async.ca.shared.global [%0], [%1], 16;\n" :: "r"(dst), "l"(src));
}
__device__ __forceinline__ void cpa_commit() { asm volatile("cp.async.commit_group;\n"); }
template <int N> __device__ __forceinline__ void cpa_wait() {
    asm volatile("cp.async.wait_group %0;\n" :: "n"(N));
}

__device__ __forceinline__ void mma_tf32(float* d, const uint32_t* a,
                                         uint32_t b0, uint32_t b1)
{
    asm volatile(
        "mma.sync.aligned.m16n8k8.row.col.f32.tf32.tf32.f32 "
        "{%0,%1,%2,%3}, {%4,%5,%6,%7}, {%8,%9}, {%0,%1,%2,%3};"
        : "+f"(d[0]), "+f"(d[1]), "+f"(d[2]), "+f"(d[3])
        : "r"(a[0]), "r"(a[1]), "r"(a[2]), "r"(a[3]), "r"(b0), "r"(b1));
}

__device__ __forceinline__ void load_stage(uint32_t sb, uint32_t sbase,
                                           const float* __restrict__ x,
                                           int blk_tok, int T, int n_tokens, int t)
{
    const int d0 = T * KC;
    // x tile: 128 rows x 128B (dst rows padded to 144B)
#pragma unroll
    for (int i = 0; i < 4; i++) {
        int c = t + i * TPB;
        int row = c >> 3, seg = c & 7;
        int tok = blk_tok + row; if (tok >= n_tokens) tok = n_tokens - 1;
        cpa16(sb + sbase + row * (XROW * 4) + seg * 16,
              x + (size_t)tok * D_MODEL + d0 + seg * 4);
    }
    // Wh tile: 32 rows x 256B (dst rows padded to 288B)
#pragma unroll
    for (int i = 0; i < 2; i++) {
        int c = t + i * TPB;
        int row = c >> 4, seg = c & 15;
        cpa16(sb + sbase + XTB + row * (WROW * 4) + seg * 16,
              Wth_g + (size_t)(d0 + row) * N_EXP + seg * 4);
    }
    // Wl tile
#pragma unroll
    for (int i = 0; i < 2; i++) {
        int c = t + i * TPB;
        int row = c >> 4, seg = c & 15;
        cpa16(sb + sbase + XTB + WTB + row * (WROW * 4) + seg * 16,
              Wtl_g + (size_t)(d0 + row) * N_EXP + seg * 4);
    }
}

__global__ void __launch_bounds__(TPB, 1)
router_kernel(const float* __restrict__ x, float* __restrict__ out,
              int n_tokens, long long out_size)
{
    extern __shared__ char smem[];
    const uint32_t sb = (uint32_t)__cvta_generic_to_shared(smem);

    const int t    = threadIdx.x;
    const int wid  = t >> 5;
    const int lane = t & 31;
    const int g    = lane >> 2;      // group 0..7
    const int tg   = lane & 3;       // thread-in-group 0..3
    const int m0   = wid * 16;       // warp's token base within CTA
    const int blk_tok = blockIdx.x * M_CTA;

    // hh-term chunk accumulator (flushed), hh master, small-terms accumulator
    float accH[8][4], masterH[8][4], accS[8][4];
#pragma unroll
    for (int n = 0; n < 8; n++)
#pragma unroll
        for (int j = 0; j < 4; j++) {
            accH[n][j] = 0.f; masterH[n][j] = 0.f; accS[n][j] = 0.f;
        }

    load_stage(sb, 0, x, blk_tok, 0, n_tokens, t);
    cpa_commit();
    load_stage(sb, STAGE, x, blk_tok, 1, n_tokens, t);
    cpa_commit();

    for (int T = 0; T < NCH; T++) {
        const int s = T & 1;
        if (T + 1 < NCH) cpa_wait<1>(); else cpa_wait<0>();
        __syncthreads();

        const float* xs = (const float*)(smem + s * STAGE);
        const float* wh = (const float*)(smem + s * STAGE + XTB);
        const float* wl = (const float*)(smem + s * STAGE + XTB + WTB);

        const float* xr0 = xs + (m0 + g) * XROW;
        const float* xr1 = xs + (m0 + g + 8) * XROW;

#pragma unroll
        for (int ks = 0; ks < 4; ks++) {
            const int k0 = ks * 8;

            // ---- A fragment: split x into tf32 hi/lo in registers ----
            float f[4] = { xr0[k0 + tg], xr1[k0 + tg],
                           xr0[k0 + tg + 4], xr1[k0 + tg + 4] };
            uint32_t ah[4], al[4];
#pragma unroll
            for (int j = 0; j < 4; j++) {
                float h = to_tf32(f[j]);
                ah[j] = __float_as_uint(h);
                al[j] = __float_as_uint(to_tf32(f[j] - h));
            }

            // ---- B fragments (already tf32 bits in smem) ----
            const float* wh0 = wh + (k0 + tg) * WROW + g;
            const float* wh1 = wh + (k0 + tg + 4) * WROW + g;
            const float* wl0 = wl + (k0 + tg) * WROW + g;
            const float* wl1 = wl + (k0 + tg + 4) * WROW + g;
            uint32_t bh0[8], bh1[8], bl0[8], bl1[8];
#pragma unroll
            for (int n = 0; n < 8; n++) {
                bh0[n] = __float_as_uint(wh0[n * 8]);
                bh1[n] = __float_as_uint(wh1[n * 8]);
                bl0[n] = __float_as_uint(wl0[n * 8]);
                bl1[n] = __float_as_uint(wl1[n * 8]);
            }

            // hh -> accH; hl + lh -> accS (|accS|~2^-11, roundings free)
#pragma unroll
            for (int n = 0; n < 8; n++) mma_tf32(accH[n], ah, bh0[n], bh1[n]);
#pragma unroll
            for (int n = 0; n < 8; n++) mma_tf32(accS[n], ah, bl0[n], bl1[n]);
#pragma unroll
            for (int n = 0; n < 8; n++) mma_tf32(accS[n], al, bh0[n], bh1[n]);
        }

        // flush hh chunk accumulator every 8 chunks (two-level accumulation)
        if ((T & 7) == 7) {
#pragma unroll
            for (int n = 0; n < 8; n++)
#pragma unroll
                for (int j = 0; j < 4; j++) {
                    masterH[n][j] += accH[n][j];
                    accH[n][j] = 0.f;
                }
        }

        __syncthreads();
        if (T + 2 < NCH) {
            load_stage(sb, s * STAGE, x, blk_tok, T + 2, n_tokens, t);
            cpa_commit();
        }
    }

    // ---- epilogue: combine terms, scatter to smem logits [128][66] ----
    float* L = (float*)smem;
#pragma unroll
    for (int n = 0; n < 8; n++) {
        int col = n * 8 + 2 * tg;
        float c0 = masterH[n][0] + accS[n][0];
        float c1 = masterH[n][1] + accS[n][1];
        float c2 = masterH[n][2] + accS[n][2];
        float c3 = masterH[n][3] + accS[n][3];
        *(float2*)&L[(m0 + g) * LROW + col]     = make_float2(c0, c1);
        *(float2*)&L[(m0 + g + 8) * LROW + col] = make_float2(c2, c3);
    }
    __syncthreads();

    if (t < M_CTA) {
        const int n = blk_tok + t;
        if (n < n_tokens) {
            float p[N_EXP];
            const float* Lr = L + t * LROW;
#pragma unroll
            for (int e = 0; e < N_EXP; e++) p[e] = Lr[e];

            float m = p[0];
#pragma unroll
            for (int e = 1; e < N_EXP; e++) m = fmaxf(m, p[e]);
            float ssum = 0.f;
#pragma unroll
            for (int e = 0; e < N_EXP; e++) { p[e] = expf(p[e] - m); ssum += p[e]; }
            float inv = 1.0f / ssum;
#pragma unroll
            for (int e = 0; e < N_EXP; e++) p[e] *= inv;

            const long long NK   = (long long)n_tokens * TOPK;
            const long long full = 2 * NK + (long long)n_tokens * N_EXP;

            if (out_size >= full) {
                float* pout = out + 2 * NK + (size_t)n * N_EXP;
#pragma unroll
                for (int e = 0; e < N_EXP; e++) pout[e] = p[e];
            }

            float tv[TOPK];
            int   ti[TOPK];
#pragma unroll
            for (int k = 0; k < TOPK; k++) { tv[k] = -1.0f; ti[k] = 0; }
#pragma unroll
            for (int e = 0; e < N_EXP; e++) {
                float v = p[e];
                if (v > tv[TOPK - 1]) {
                    tv[TOPK - 1] = v;
                    ti[TOPK - 1] = e;
#pragma unroll
                    for (int j = TOPK - 1; j > 0; j--) {
                        if (tv[j] > tv[j - 1]) {
                            float tf = tv[j]; tv[j] = tv[j - 1]; tv[j - 1] = tf;
                            int   tn = ti[j]; ti[j] = ti[j - 1]; ti[j - 1] = tn;
                        }
                    }
                }
            }
            float ws = 0.f;
#pragma unroll
            for (int k = 0; k < TOPK; k++) ws += tv[k];
            float winv = 1.0f / (ws + 1e-9f);

            if (out_size >= 2 * NK) {
#pragma unroll
                for (int k = 0; k < TOPK; k++) {
                    out[(size_t)n * TOPK + k]      = (float)ti[k];
                    out[NK + (size_t)n * TOPK + k] = tv[k] * winv;
                }
            } else if (out_size >= NK) {
#pragma unroll
                for (int k = 0; k < TOPK; k++)
                    out[(size_t)n * TOPK + k] = (float)ti[k];
            }
        }
    }
}

extern "C" void kernel_launch(void* const* d_in, const int* in_sizes, int n_in,
                              void* d_out, int out_size)
{
    const float* x = (const float*)d_in[0];
    const float* W = (const float*)d_in[1];
    int n_tokens = in_sizes[0] / D_MODEL;            // 16384

    split_W<<<(N_EXP * D_MODEL + 255) / 256, 256>>>(W);

    cudaFuncSetAttribute(router_kernel,
                         cudaFuncAttributeMaxDynamicSharedMemorySize, SMEMB);
    int grid = (n_tokens + M_CTA - 1) / M_CTA;       // 128
    router_kernel<<<grid, TPB, SMEMB>>>(x, (float*)d_out, n_tokens,
                                        (long long)out_size);
}